// round 6
// baseline (speedup 1.0000x reference)
#include <cuda_runtime.h>
#include <cuda_bf16.h>
#include <cstdint>

#define SEQ 2048
#define NH 16

// ---------------- scratch (static __device__, allocation-free) ----------------
__device__ float g_XQKV[4096 * 2048];      // [b*s][xq(1024) | xk(512) | xv(512)]
__device__ float g_Qt[32 * 64 * SEQ];      // [bh][d][s]  (roped, *0.5)
__device__ float g_Kt[32 * 64 * SEQ];      // [bh][d][s]  (roped, expanded)
__device__ float g_Vh[32 * SEQ * 32];      // [bh][s][dd] (32 distinct V dims/head)
__device__ float g_Of[4096 * 512];         // [b*s][h*32+dd]
__device__ float g_Wof[512 * 1024];        // folded Wo

// ---------------- generic fp32 SGEMM: 128x128x8 tiles, 8x8/thread ----------------
__global__ void __launch_bounds__(256) sgemm128(
    const float* __restrict__ A, const float* __restrict__ Bm, float* __restrict__ C,
    int K, int ldb, int ldc)
{
    __shared__ float As[8][132];
    __shared__ float Bs[8][128];
    const int tid = threadIdx.x;
    const int tx = tid & 15, ty = tid >> 4;
    const int m0 = blockIdx.y * 128, n0 = blockIdx.x * 128;
    const int arow = tid >> 1, acol = (tid & 1) * 4;
    const int brow = tid >> 5, bcol = (tid & 31) * 4;
    const float* Ap = A + (size_t)(m0 + arow) * K + acol;
    const float* Bp = Bm + (size_t)brow * ldb + n0 + bcol;

    float acc[8][8];
#pragma unroll
    for (int i = 0; i < 8; i++)
#pragma unroll
        for (int j = 0; j < 8; j++) acc[i][j] = 0.f;

    for (int k0 = 0; k0 < K; k0 += 8) {
        float4 av = *(const float4*)(Ap + k0);
        float4 bv = *(const float4*)(Bp + (size_t)k0 * ldb);
        __syncthreads();
        As[acol + 0][arow] = av.x;
        As[acol + 1][arow] = av.y;
        As[acol + 2][arow] = av.z;
        As[acol + 3][arow] = av.w;
        *(float4*)&Bs[brow][bcol] = bv;
        __syncthreads();
#pragma unroll
        for (int kk = 0; kk < 8; kk++) {
            float a[8], b[8];
            *(float4*)&a[0] = *(const float4*)&As[kk][ty * 8];
            *(float4*)&a[4] = *(const float4*)&As[kk][ty * 8 + 4];
            *(float4*)&b[0] = *(const float4*)&Bs[kk][tx * 8];
            *(float4*)&b[4] = *(const float4*)&Bs[kk][tx * 8 + 4];
#pragma unroll
            for (int i = 0; i < 8; i++)
#pragma unroll
                for (int j = 0; j < 8; j++)
                    acc[i][j] += a[i] * b[j];
        }
    }
#pragma unroll
    for (int i = 0; i < 8; i++) {
        float* cp = C + (size_t)(m0 + ty * 8 + i) * ldc + n0 + tx * 8;
        *(float4*)cp       = make_float4(acc[i][0], acc[i][1], acc[i][2], acc[i][3]);
        *(float4*)(cp + 4) = make_float4(acc[i][4], acc[i][5], acc[i][6], acc[i][7]);
    }
}

// ---------------- RoPE (empirically verified FLIPPED rotation) + expansion -----
// Probe R5 proved the executed reference uses the opposite rotation sign:
//   re = xe*cos + xo*sin ; im = -xe*sin + xo*cos   (achieved via sn = -sn)
__global__ void rope_scatter(const float* __restrict__ X)
{
    const int row = blockIdx.x;           // b*2048 + s
    const int s = row & (SEQ - 1);
    const int b = row >> 11;
    const int t = threadIdx.x;            // 0..511
    const int h = t >> 5, i = t & 31;
    const float* xr = X + (size_t)row * 2048;

    const float pos = (float)(s + 1);
    const float theta = exp10f(-(float)i);
    float c, sn;
    sincosf(pos * theta, &c, &sn);
    sn = -sn;                             // verified convention flip (R5 probe)

    const size_t bh = (size_t)(b * NH + h);
    const size_t qkbase = bh * 64 * SEQ + (size_t)(2 * i) * SEQ + s;

    const float xe = xr[h * 64 + 2 * i];
    const float xo = xr[h * 64 + 2 * i + 1];
    g_Qt[qkbase]       = (xe * c - xo * sn) * 0.5f;   // softmax scale folded into Q
    g_Qt[qkbase + SEQ] = (xe * sn + xo * c) * 0.5f;

    const float ko = xr[1024 + h * 32 + i];
    g_Kt[qkbase]       = ko * (c - sn);
    g_Kt[qkbase + SEQ] = ko * (c + sn);

    g_Vh[(bh * SEQ + s) * 32 + i] = xr[1536 + t];
}

// ---------------- fold Wo rows for duplicated V features ----------------
__global__ void fold_wo(const float* __restrict__ Wo)
{
    const int idx = blockIdx.x * blockDim.x + threadIdx.x;   // 512*1024
    const int i = idx >> 10, n = idx & 1023;
    const int j0 = (i >> 5) * 64 + (i & 31) * 2;
    g_Wof[idx] = Wo[(size_t)j0 * 1024 + n] + Wo[(size_t)(j0 + 1) * 1024 + n];
}

// ---------------- flash attention: 64(Q) x 64(K) tiles, V dim 32 ----------------
__global__ void __launch_bounds__(256) flash_attn(float* __restrict__ Of)
{
    __shared__ float Qs[64][64];   // [d][row]
    __shared__ float KP[64][68];   // Ks as [d][col]; reused as P [row][col] (aliased)
    __shared__ float Vs[64][32];   // [col][dd]

    const int bh = blockIdx.y;
    const int q0 = blockIdx.x * 64;
    const int tid = threadIdx.x;
    const int tx = tid & 15, ty = tid >> 4;
    const float* Qb = g_Qt + (size_t)bh * 64 * SEQ;
    const float* Kb = g_Kt + (size_t)bh * 64 * SEQ;
    const float* Vb = g_Vh + (size_t)bh * SEQ * 32;

    {   // load Q tile once (persistent)
        const int d = tid >> 4;
        const int c4 = (tid & 15) * 4;
#pragma unroll
        for (int rr = 0; rr < 4; rr++) {
            const int dd = rr * 16 + d;
            *(float4*)&Qs[dd][c4] = *(const float4*)&Qb[(size_t)dd * SEQ + q0 + c4];
        }
    }

    float m_[4], l_[4], o_[4][2];
#pragma unroll
    for (int i = 0; i < 4; i++) { m_[i] = -1e30f; l_[i] = 0.f; o_[i][0] = 0.f; o_[i][1] = 0.f; }

    for (int it = 0; it < 32; it++) {
        const int k0 = it * 64;
        __syncthreads();   // prev iter's P/V reads done
        {
            const int d = tid >> 4;
            const int c4 = (tid & 15) * 4;
#pragma unroll
            for (int rr = 0; rr < 4; rr++) {
                const int dd = rr * 16 + d;
                *(float4*)&KP[dd][c4] = *(const float4*)&Kb[(size_t)dd * SEQ + k0 + c4];
            }
            const int cv = tid >> 3;
            const int v4 = (tid & 7) * 4;
#pragma unroll
            for (int rr = 0; rr < 2; rr++) {
                const int cc = rr * 32 + cv;
                *(float4*)&Vs[cc][v4] = *(const float4*)&Vb[(size_t)(k0 + cc) * 32 + v4];
            }
        }
        __syncthreads();

        // S = Q^T K  (4x4 per thread)
        float sacc[4][4];
#pragma unroll
        for (int i = 0; i < 4; i++)
#pragma unroll
            for (int j = 0; j < 4; j++) sacc[i][j] = 0.f;

#pragma unroll 8
        for (int d = 0; d < 64; d++) {
            float a[4], bb[4];
            *(float4*)&a[0] = *(const float4*)&Qs[d][ty * 4];
            *(float4*)&bb[0] = *(const float4*)&KP[d][tx * 4];
#pragma unroll
            for (int i = 0; i < 4; i++)
#pragma unroll
                for (int j = 0; j < 4; j++)
                    sacc[i][j] += a[i] * bb[j];
        }
        __syncthreads();   // everyone done reading K tile before P overwrites it

        // online softmax (rows owned by same ty; reduce across tx = 16-lane segments)
#pragma unroll
        for (int i = 0; i < 4; i++) {
            float mx = fmaxf(fmaxf(sacc[i][0], sacc[i][1]), fmaxf(sacc[i][2], sacc[i][3]));
#pragma unroll
            for (int off = 8; off > 0; off >>= 1)
                mx = fmaxf(mx, __shfl_xor_sync(0xffffffffu, mx, off, 16));
            const float mnew = fmaxf(m_[i], mx);
            const float corr = __expf(m_[i] - mnew);
            float rs = 0.f;
#pragma unroll
            for (int j = 0; j < 4; j++) {
                const float p = __expf(sacc[i][j] - mnew);
                sacc[i][j] = p;
                rs += p;
            }
#pragma unroll
            for (int off = 8; off > 0; off >>= 1)
                rs += __shfl_xor_sync(0xffffffffu, rs, off, 16);
            m_[i] = mnew;
            l_[i] = l_[i] * corr + rs;
            o_[i][0] *= corr;
            o_[i][1] *= corr;
            KP[ty * 4 + i][tx * 4 + 0] = sacc[i][0];
            KP[ty * 4 + i][tx * 4 + 1] = sacc[i][1];
            KP[ty * 4 + i][tx * 4 + 2] = sacc[i][2];
            KP[ty * 4 + i][tx * 4 + 3] = sacc[i][3];
        }
        __syncthreads();

        // O += P @ V  (V dim = 32; thread owns cols tx*2, tx*2+1)
#pragma unroll 4
        for (int c0 = 0; c0 < 64; c0 += 4) {
            float pr[4][4];
#pragma unroll
            for (int i = 0; i < 4; i++)
                *(float4*)&pr[i][0] = *(const float4*)&KP[ty * 4 + i][c0];
#pragma unroll
            for (int u = 0; u < 4; u++) {
                const float2 v = *(const float2*)&Vs[c0 + u][tx * 2];
#pragma unroll
                for (int i = 0; i < 4; i++) {
                    o_[i][0] += pr[i][u] * v.x;
                    o_[i][1] += pr[i][u] * v.y;
                }
            }
        }
    }

    const int b = bh >> 4, h = bh & 15;
#pragma unroll
    for (int i = 0; i < 4; i++) {
        const float inv = 1.0f / l_[i];
        const int srow = q0 + ty * 4 + i;
        const float2 ov = make_float2(o_[i][0] * inv, o_[i][1] * inv);
        *(float2*)&Of[(((size_t)(b * SEQ + srow)) * NH + h) * 32 + tx * 2] = ov;
    }
}

// ---------------- launch ----------------
extern "C" void kernel_launch(void* const* d_in, const int* in_sizes, int n_in,
                              void* d_out, int out_size)
{
    int iq = 0, i1M[2] = {2, 5}, i05[2] = {3, 4};
    {
        int n1 = 0, n0 = 0;
        for (int i = 0; i < n_in; i++) {
            const int sz = in_sizes[i];
            if (sz == 4194304) iq = i;
            else if (sz == 1048576) { if (n1 < 2) i1M[n1++] = i; }
            else if (sz == 524288)  { if (n0 < 2) i05[n0++] = i; }
        }
    }
    const bool alpha = (iq != 0);
    const float* q  = (const float*)d_in[iq];
    const float* Wq = (const float*)d_in[alpha ? i1M[1] : i1M[0]];
    const float* Wo = (const float*)d_in[alpha ? i1M[0] : i1M[1]];
    const float* Wk = (const float*)d_in[i05[0]];
    const float* Wv = (const float*)d_in[i05[1]];
    float* out = (float*)d_out;

    float *XQKV, *Of, *Wof;
    cudaGetSymbolAddress((void**)&XQKV, g_XQKV);
    cudaGetSymbolAddress((void**)&Of, g_Of);
    cudaGetSymbolAddress((void**)&Wof, g_Wof);

    const dim3 blk(256);
    sgemm128<<<dim3(8, 32), blk>>>(q, Wq, XQKV,        1024, 1024, 2048);
    sgemm128<<<dim3(4, 32), blk>>>(q, Wk, XQKV + 1024, 1024,  512, 2048);
    sgemm128<<<dim3(4, 32), blk>>>(q, Wv, XQKV + 1536, 1024,  512, 2048);
    rope_scatter<<<4096, 512>>>(XQKV);
    fold_wo<<<2048, 256>>>(Wo);
    flash_attn<<<dim3(32, 32), blk>>>(Of);
    sgemm128<<<dim3(8, 32), blk>>>(Of, Wof, out, 512, 1024, 1024);
}

// round 7
// speedup vs baseline: 2.7150x; 2.7150x over previous
#include <cuda_runtime.h>
#include <cuda_bf16.h>
#include <cstdint>

using bf16 = __nv_bfloat16;

#define SEQ 2048
#define NH 16

// ---------------- scratch (static __device__, allocation-free) ----------------
__device__ float g_XQKV[4096 * 2048];          // fp32 [b*s][xq|xk|xv]
__device__ bf16  g_qh[4096 * 1024],  g_ql[4096 * 1024];     // split input q
__device__ bf16  g_wqh[1024 * 1024], g_wql[1024 * 1024];
__device__ bf16  g_wkh[1024 * 512],  g_wkl[1024 * 512];
__device__ bf16  g_wvh[1024 * 512],  g_wvl[1024 * 512];
__device__ bf16  g_Qh[32u * SEQ * 64], g_Ql[32u * SEQ * 64];  // roped, *0.5, [bh][s][d]
__device__ bf16  g_Kh[32u * SEQ * 64], g_Kl[32u * SEQ * 64];
__device__ bf16  g_Vh[32u * SEQ * 32], g_Vl[32u * SEQ * 32];  // 32 distinct dims
__device__ bf16  g_ofh[4096 * 512],  g_ofl[4096 * 512];       // attention out split
__device__ bf16  g_wofh[512 * 1024], g_wofl[512 * 1024];      // folded Wo split

// ---------------- helpers ----------------
__device__ __forceinline__ uint32_t saddr(const void* p) {
    return (uint32_t)__cvta_generic_to_shared(p);
}
__device__ __forceinline__ void split2(float x0, float x1, uint32_t& h, uint32_t& l) {
    __nv_bfloat162 H = __floats2bfloat162_rn(x0, x1);
    float f0 = __bfloat162float(H.x), f1 = __bfloat162float(H.y);
    __nv_bfloat162 L = __floats2bfloat162_rn(x0 - f0, x1 - f1);
    h = *(uint32_t*)&H; l = *(uint32_t*)&L;
}
__device__ __forceinline__ void mma16816(float* c, const uint32_t* a, uint32_t b0, uint32_t b1) {
    asm volatile(
        "mma.sync.aligned.m16n8k16.row.col.f32.bf16.bf16.f32 "
        "{%0,%1,%2,%3}, {%4,%5,%6,%7}, {%8,%9}, {%0,%1,%2,%3};"
        : "+f"(c[0]), "+f"(c[1]), "+f"(c[2]), "+f"(c[3])
        : "r"(a[0]), "r"(a[1]), "r"(a[2]), "r"(a[3]), "r"(b0), "r"(b1));
}
__device__ __forceinline__ void ldsm4(uint32_t* r, uint32_t a) {
    asm volatile("ldmatrix.sync.aligned.m8n8.x4.shared.b16 {%0,%1,%2,%3}, [%4];"
                 : "=r"(r[0]), "=r"(r[1]), "=r"(r[2]), "=r"(r[3]) : "r"(a));
}
__device__ __forceinline__ void ldsm4t(uint32_t* r, uint32_t a) {
    asm volatile("ldmatrix.sync.aligned.m8n8.x4.trans.shared.b16 {%0,%1,%2,%3}, [%4];"
                 : "=r"(r[0]), "=r"(r[1]), "=r"(r[2]), "=r"(r[3]) : "r"(a));
}

// ---------------- fp32 -> split bf16 ----------------
__global__ void split4(const float* __restrict__ x, bf16* __restrict__ h,
                       bf16* __restrict__ l, int n)
{
    int i = (blockIdx.x * blockDim.x + threadIdx.x) * 4;
    if (i >= n) return;
    float4 v = *(const float4*)(x + i);
    uint32_t h0, l0, h1, l1;
    split2(v.x, v.y, h0, l0);
    split2(v.z, v.w, h1, l1);
    *(uint32_t*)(h + i) = h0; *(uint32_t*)(h + i + 2) = h1;
    *(uint32_t*)(l + i) = l0; *(uint32_t*)(l + i + 2) = l1;
}

// ---------------- split-bf16 GEMM (3-term), C fp32 = A[MxK] B[KxN] ----------------
// block 128x64, 8 warps (4x2), warp tile 32x32, K-step 32
__global__ void __launch_bounds__(256) gemm_bf16x3(
    const bf16* __restrict__ Ah, const bf16* __restrict__ Al,
    const bf16* __restrict__ Bh, const bf16* __restrict__ Bl,
    float* __restrict__ C, int K, int ldb, int ldc)
{
    __shared__ bf16 sAh[128][40], sAl[128][40];
    __shared__ bf16 sBh[32][72],  sBl[32][72];
    const int tid = threadIdx.x, wid = tid >> 5, lane = tid & 31;
    const int m0 = blockIdx.y * 128, n0 = blockIdx.x * 64;
    const int mw = (wid >> 1) * 32, nw = (wid & 1) * 32;

    float c[2][4][4];
#pragma unroll
    for (int mt = 0; mt < 2; mt++)
#pragma unroll
        for (int nt = 0; nt < 4; nt++)
#pragma unroll
            for (int k = 0; k < 4; k++) c[mt][nt][k] = 0.f;

    const int arow = tid >> 2, acol = (tid & 3) * 8;
    const int brow = tid >> 3, bcol = (tid & 7) * 8;

    for (int k0 = 0; k0 < K; k0 += 32) {
        __syncthreads();
#pragma unroll
        for (int p = 0; p < 2; p++) {
            const int r = arow + p * 64;
            *(uint4*)&sAh[r][acol] = *(const uint4*)&Ah[(size_t)(m0 + r) * K + k0 + acol];
            *(uint4*)&sAl[r][acol] = *(const uint4*)&Al[(size_t)(m0 + r) * K + k0 + acol];
        }
        *(uint4*)&sBh[brow][bcol] = *(const uint4*)&Bh[(size_t)(k0 + brow) * ldb + n0 + bcol];
        *(uint4*)&sBl[brow][bcol] = *(const uint4*)&Bl[(size_t)(k0 + brow) * ldb + n0 + bcol];
        __syncthreads();

#pragma unroll
        for (int kk = 0; kk < 32; kk += 16) {
            uint32_t ah[2][4], al[2][4];
#pragma unroll
            for (int mt = 0; mt < 2; mt++) {
                const int rr = mw + mt * 16 + (lane & 15);
                const int cc = kk + (lane >> 4) * 8;
                ldsm4(ah[mt], saddr(&sAh[rr][cc]));
                ldsm4(al[mt], saddr(&sAl[rr][cc]));
            }
            uint32_t bh[4][2], bl[4][2];
#pragma unroll
            for (int np = 0; np < 2; np++) {
                const int rr = kk + (lane & 7) + ((lane >> 3) & 1) * 8;
                const int cc = nw + np * 16 + (lane >> 4) * 8;
                uint32_t r4[4];
                ldsm4t(r4, saddr(&sBh[rr][cc]));
                bh[np*2][0] = r4[0]; bh[np*2][1] = r4[1];
                bh[np*2+1][0] = r4[2]; bh[np*2+1][1] = r4[3];
                ldsm4t(r4, saddr(&sBl[rr][cc]));
                bl[np*2][0] = r4[0]; bl[np*2][1] = r4[1];
                bl[np*2+1][0] = r4[2]; bl[np*2+1][1] = r4[3];
            }
#pragma unroll
            for (int mt = 0; mt < 2; mt++)
#pragma unroll
                for (int nt = 0; nt < 4; nt++) {
                    mma16816(c[mt][nt], ah[mt], bh[nt][0], bh[nt][1]);
                    mma16816(c[mt][nt], ah[mt], bl[nt][0], bl[nt][1]);
                    mma16816(c[mt][nt], al[mt], bh[nt][0], bh[nt][1]);
                }
        }
    }
#pragma unroll
    for (int mt = 0; mt < 2; mt++) {
        const int r0 = m0 + mw + mt * 16 + (lane >> 2);
#pragma unroll
        for (int nt = 0; nt < 4; nt++) {
            const int cc = n0 + nw + nt * 8 + (lane & 3) * 2;
            *(float2*)&C[(size_t)r0 * ldc + cc]       = make_float2(c[mt][nt][0], c[mt][nt][1]);
            *(float2*)&C[(size_t)(r0 + 8) * ldc + cc] = make_float2(c[mt][nt][2], c[mt][nt][3]);
        }
    }
}

// ---------------- RoPE (verified flipped rotation) -> split bf16, row-major ----
__global__ void rope_scatter(const float* __restrict__ X)
{
    const int row = blockIdx.x;           // b*2048 + s
    const int s = row & (SEQ - 1), b = row >> 11;
    const int t = threadIdx.x;            // 0..511
    const int h = t >> 5, i = t & 31;
    const float* xr = X + (size_t)row * 2048;

    float c, sn;
    sincosf((float)(s + 1) * exp10f(-(float)i), &c, &sn);
    sn = -sn;                             // R5-verified convention flip

    const size_t bh = (size_t)(b * NH + h);
    const size_t base = (bh * SEQ + s) * 64 + 2 * i;

    const float xe = xr[h * 64 + 2 * i];
    const float xo = xr[h * 64 + 2 * i + 1];
    uint32_t hh, ll;
    split2((xe * c - xo * sn) * 0.5f, (xe * sn + xo * c) * 0.5f, hh, ll);
    *(uint32_t*)&g_Qh[base] = hh; *(uint32_t*)&g_Ql[base] = ll;

    const float ko = xr[1024 + h * 32 + i];
    split2(ko * (c - sn), ko * (c + sn), hh, ll);
    *(uint32_t*)&g_Kh[base] = hh; *(uint32_t*)&g_Kl[base] = ll;

    const float v = xr[1536 + t];
    const size_t vb = (bh * SEQ + s) * 32 + i;
    bf16 vh = __float2bfloat16_rn(v);
    g_Vh[vb] = vh;
    g_Vl[vb] = __float2bfloat16_rn(v - __bfloat162float(vh));
}

// ---------------- fold Wo rows for duplicated V features -> split ----------------
__global__ void fold_wo(const float* __restrict__ Wo)
{
    const int idx = blockIdx.x * blockDim.x + threadIdx.x;   // 512*1024
    const int i = idx >> 10, n = idx & 1023;
    const int j0 = (i >> 5) * 64 + (i & 31) * 2;
    const float w = Wo[(size_t)j0 * 1024 + n] + Wo[(size_t)(j0 + 1) * 1024 + n];
    bf16 wh = __float2bfloat16_rn(w);
    g_wofh[idx] = wh;
    g_wofl[idx] = __float2bfloat16_rn(w - __bfloat162float(wh));
}

// ---------------- flash attention, split-bf16 mma ----------------
// block: (q-tile 128) x (bh). 8 warps x 16 q-rows. K-tile 64 keys, V-dim 32.
__global__ void __launch_bounds__(256) flash_mma()
{
    __shared__ bf16 sKh[64][72], sKl[64][72];
    __shared__ bf16 sVh[64][40], sVl[64][40];
    const int tid = threadIdx.x, wid = tid >> 5, lane = tid & 31;
    const int bh = blockIdx.y, q0 = blockIdx.x * 128;
    const int b = bh >> 4, h = bh & 15;
    const int r = lane >> 2, c2 = (lane & 3) * 2;

    // Q fragments straight from global (one-time)
    uint32_t qh[4][4], ql[4][4];
    {
        const size_t qrow = ((size_t)bh * SEQ + q0 + wid * 16 + r) * 64;
#pragma unroll
        for (int kk = 0; kk < 4; kk++) {
            const size_t o0 = qrow + kk * 16 + c2;
            qh[kk][0] = *(const uint32_t*)&g_Qh[o0];
            qh[kk][1] = *(const uint32_t*)&g_Qh[o0 + 8u * 64];
            qh[kk][2] = *(const uint32_t*)&g_Qh[o0 + 8];
            qh[kk][3] = *(const uint32_t*)&g_Qh[o0 + 8u * 64 + 8];
            ql[kk][0] = *(const uint32_t*)&g_Ql[o0];
            ql[kk][1] = *(const uint32_t*)&g_Ql[o0 + 8u * 64];
            ql[kk][2] = *(const uint32_t*)&g_Ql[o0 + 8];
            ql[kk][3] = *(const uint32_t*)&g_Ql[o0 + 8u * 64 + 8];
        }
    }

    float o[4][4];
#pragma unroll
    for (int nt = 0; nt < 4; nt++)
#pragma unroll
        for (int k = 0; k < 4; k++) o[nt][k] = 0.f;
    float m0r = -1e30f, m1r = -1e30f, l0r = 0.f, l1r = 0.f;

    const bf16* Khg = g_Kh + (size_t)bh * SEQ * 64;
    const bf16* Klg = g_Kl + (size_t)bh * SEQ * 64;
    const bf16* Vhg = g_Vh + (size_t)bh * SEQ * 32;
    const bf16* Vlg = g_Vl + (size_t)bh * SEQ * 32;

    const int krow = tid >> 2, kcol = (tid & 3) * 16;
    const int vcol = (tid & 3) * 8;

    for (int it = 0; it < 32; it++) {
        const int k0 = it * 64;
        __syncthreads();
        *(uint4*)&sKh[krow][kcol]     = *(const uint4*)&Khg[(size_t)(k0 + krow) * 64 + kcol];
        *(uint4*)&sKh[krow][kcol + 8] = *(const uint4*)&Khg[(size_t)(k0 + krow) * 64 + kcol + 8];
        *(uint4*)&sKl[krow][kcol]     = *(const uint4*)&Klg[(size_t)(k0 + krow) * 64 + kcol];
        *(uint4*)&sKl[krow][kcol + 8] = *(const uint4*)&Klg[(size_t)(k0 + krow) * 64 + kcol + 8];
        *(uint4*)&sVh[krow][vcol]     = *(const uint4*)&Vhg[(size_t)(k0 + krow) * 32 + vcol];
        *(uint4*)&sVl[krow][vcol]     = *(const uint4*)&Vlg[(size_t)(k0 + krow) * 32 + vcol];
        __syncthreads();

        // S = Q K^T
        float s[8][4];
#pragma unroll
        for (int nt = 0; nt < 8; nt++)
#pragma unroll
            for (int k = 0; k < 4; k++) s[nt][k] = 0.f;

#pragma unroll
        for (int kk = 0; kk < 4; kk++) {
#pragma unroll
            for (int np = 0; np < 4; np++) {
                const int rr = np * 16 + (lane & 7) + ((lane >> 4) << 3);
                const int cc = kk * 16 + ((lane >> 3) & 1) * 8;
                uint32_t rH[4], rL[4];
                ldsm4(rH, saddr(&sKh[rr][cc]));
                ldsm4(rL, saddr(&sKl[rr][cc]));
#pragma unroll
                for (int t2 = 0; t2 < 2; t2++) {
                    const int nt = np * 2 + t2;
                    mma16816(s[nt], qh[kk], rH[t2*2], rH[t2*2+1]);
                    mma16816(s[nt], qh[kk], rL[t2*2], rL[t2*2+1]);
                    mma16816(s[nt], ql[kk], rH[t2*2], rH[t2*2+1]);
                }
            }
        }

        // online softmax (rows r and r+8 of this warp's 16)
        float mx0 = -1e30f, mx1 = -1e30f;
#pragma unroll
        for (int nt = 0; nt < 8; nt++) {
            mx0 = fmaxf(mx0, fmaxf(s[nt][0], s[nt][1]));
            mx1 = fmaxf(mx1, fmaxf(s[nt][2], s[nt][3]));
        }
        mx0 = fmaxf(mx0, __shfl_xor_sync(0xffffffffu, mx0, 1));
        mx0 = fmaxf(mx0, __shfl_xor_sync(0xffffffffu, mx0, 2));
        mx1 = fmaxf(mx1, __shfl_xor_sync(0xffffffffu, mx1, 1));
        mx1 = fmaxf(mx1, __shfl_xor_sync(0xffffffffu, mx1, 2));
        const float mn0 = fmaxf(m0r, mx0), mn1 = fmaxf(m1r, mx1);
        const float cr0 = __expf(m0r - mn0), cr1 = __expf(m1r - mn1);
        float sum0 = 0.f, sum1 = 0.f;
#pragma unroll
        for (int nt = 0; nt < 8; nt++) {
            s[nt][0] = __expf(s[nt][0] - mn0); sum0 += s[nt][0];
            s[nt][1] = __expf(s[nt][1] - mn0); sum0 += s[nt][1];
            s[nt][2] = __expf(s[nt][2] - mn1); sum1 += s[nt][2];
            s[nt][3] = __expf(s[nt][3] - mn1); sum1 += s[nt][3];
        }
        sum0 += __shfl_xor_sync(0xffffffffu, sum0, 1);
        sum0 += __shfl_xor_sync(0xffffffffu, sum0, 2);
        sum1 += __shfl_xor_sync(0xffffffffu, sum1, 1);
        sum1 += __shfl_xor_sync(0xffffffffu, sum1, 2);
        l0r = l0r * cr0 + sum0;
        l1r = l1r * cr1 + sum1;
        m0r = mn0; m1r = mn1;
#pragma unroll
        for (int nt = 0; nt < 4; nt++) {
            o[nt][0] *= cr0; o[nt][1] *= cr0;
            o[nt][2] *= cr1; o[nt][3] *= cr1;
        }

        // P fragments (split) from S registers
        uint32_t ph[4][4], pl[4][4];
#pragma unroll
        for (int kk = 0; kk < 4; kk++) {
            split2(s[2*kk][0],   s[2*kk][1],   ph[kk][0], pl[kk][0]);
            split2(s[2*kk][2],   s[2*kk][3],   ph[kk][1], pl[kk][1]);
            split2(s[2*kk+1][0], s[2*kk+1][1], ph[kk][2], pl[kk][2]);
            split2(s[2*kk+1][2], s[2*kk+1][3], ph[kk][3], pl[kk][3]);
        }

        // O += P V
#pragma unroll
        for (int kk = 0; kk < 4; kk++) {
#pragma unroll
            for (int np = 0; np < 2; np++) {
                const int rr = kk * 16 + (lane & 7) + ((lane >> 3) & 1) * 8;
                const int cc = np * 16 + (lane >> 4) * 8;
                uint32_t rH[4], rL[4];
                ldsm4t(rH, saddr(&sVh[rr][cc]));
                ldsm4t(rL, saddr(&sVl[rr][cc]));
#pragma unroll
                for (int t2 = 0; t2 < 2; t2++) {
                    const int nt = np * 2 + t2;
                    mma16816(o[nt], ph[kk], rH[t2*2], rH[t2*2+1]);
                    mma16816(o[nt], ph[kk], rL[t2*2], rL[t2*2+1]);
                    mma16816(o[nt], pl[kk], rH[t2*2], rH[t2*2+1]);
                }
            }
        }
    }

    // epilogue: normalize, split, store to Of (A-matrix of output GEMM)
    const float i0 = 1.f / l0r, i1 = 1.f / l1r;
    const size_t row0 = (size_t)b * SEQ + q0 + wid * 16 + r;
#pragma unroll
    for (int nt = 0; nt < 4; nt++) {
        const int cc = h * 32 + nt * 8 + c2;
        uint32_t hh, ll;
        split2(o[nt][0] * i0, o[nt][1] * i0, hh, ll);
        *(uint32_t*)&g_ofh[row0 * 512 + cc] = hh;
        *(uint32_t*)&g_ofl[row0 * 512 + cc] = ll;
        split2(o[nt][2] * i1, o[nt][3] * i1, hh, ll);
        *(uint32_t*)&g_ofh[(row0 + 8) * 512 + cc] = hh;
        *(uint32_t*)&g_ofl[(row0 + 8) * 512 + cc] = ll;
    }
}

// ---------------- launch ----------------
extern "C" void kernel_launch(void* const* d_in, const int* in_sizes, int n_in,
                              void* d_out, int out_size)
{
    int iq = 0, i1M[2] = {2, 5}, i05[2] = {3, 4};
    {
        int n1 = 0, n0 = 0;
        for (int i = 0; i < n_in; i++) {
            const int sz = in_sizes[i];
            if (sz == 4194304) iq = i;
            else if (sz == 1048576) { if (n1 < 2) i1M[n1++] = i; }
            else if (sz == 524288)  { if (n0 < 2) i05[n0++] = i; }
        }
    }
    const bool alpha = (iq != 0);
    const float* q  = (const float*)d_in[iq];
    const float* Wq = (const float*)d_in[alpha ? i1M[1] : i1M[0]];
    const float* Wo = (const float*)d_in[alpha ? i1M[0] : i1M[1]];
    const float* Wk = (const float*)d_in[i05[0]];
    const float* Wv = (const float*)d_in[i05[1]];
    float* out = (float*)d_out;

    float* XQKV;  cudaGetSymbolAddress((void**)&XQKV, g_XQKV);
    bf16 *qh, *ql, *wqh, *wql, *wkh, *wkl, *wvh, *wvl, *ofh, *ofl, *wofh, *wofl;
    cudaGetSymbolAddress((void**)&qh, g_qh);   cudaGetSymbolAddress((void**)&ql, g_ql);
    cudaGetSymbolAddress((void**)&wqh, g_wqh); cudaGetSymbolAddress((void**)&wql, g_wql);
    cudaGetSymbolAddress((void**)&wkh, g_wkh); cudaGetSymbolAddress((void**)&wkl, g_wkl);
    cudaGetSymbolAddress((void**)&wvh, g_wvh); cudaGetSymbolAddress((void**)&wvl, g_wvl);
    cudaGetSymbolAddress((void**)&ofh, g_ofh); cudaGetSymbolAddress((void**)&ofl, g_ofl);
    cudaGetSymbolAddress((void**)&wofh, g_wofh); cudaGetSymbolAddress((void**)&wofl, g_wofl);

    // split conversions
    split4<<<4096, 256>>>(q,  qh,  ql,  4194304);
    split4<<<1024, 256>>>(Wq, wqh, wql, 1048576);
    split4<<<512,  256>>>(Wk, wkh, wkl, 524288);
    split4<<<512,  256>>>(Wv, wvh, wvl, 524288);
    fold_wo<<<2048, 256>>>(Wo);

    // projections (tensor cores)
    gemm_bf16x3<<<dim3(16, 32), 256>>>(qh, ql, wqh, wql, XQKV,        1024, 1024, 2048);
    gemm_bf16x3<<<dim3(8, 32),  256>>>(qh, ql, wkh, wkl, XQKV + 1024, 1024,  512, 2048);
    gemm_bf16x3<<<dim3(8, 32),  256>>>(qh, ql, wvh, wvl, XQKV + 1536, 1024,  512, 2048);

    rope_scatter<<<4096, 512>>>(XQKV);
    flash_mma<<<dim3(16, 32), 256>>>();

    // output projection (folded Wo, K = 512)
    gemm_bf16x3<<<dim3(16, 32), 256>>>(ofh, ofl, wofh, wofl, out, 512, 1024, 1024);
}

// round 9
// speedup vs baseline: 2.9501x; 1.0866x over previous
#include <cuda_runtime.h>
#include <cuda_bf16.h>
#include <cstdint>

using bf16 = __nv_bfloat16;

#define SEQ 2048
#define NH 16

// ---------------- scratch (static __device__, allocation-free) ----------------
__device__ float g_XQKV[4096 * 2048];          // fp32 [b*s][xq|xk|xv]
__device__ bf16  g_qh[4096 * 1024],  g_ql[4096 * 1024];       // split input q
__device__ bf16  g_wch[1024 * 2048], g_wcl[1024 * 2048];      // concat W [k][Wq|Wk|Wv]
__device__ bf16  g_Qh[32u * SEQ * 64], g_Ql[32u * SEQ * 64];  // roped, *0.5, [bh][s][d]
__device__ bf16  g_Kh[32u * SEQ * 64], g_Kl[32u * SEQ * 64];
__device__ bf16  g_Vh[32u * SEQ * 32], g_Vl[32u * SEQ * 32];
__device__ bf16  g_ofh[4096 * 512],  g_ofl[4096 * 512];       // attention out split
__device__ bf16  g_wofh[512 * 1024], g_wofl[512 * 1024];      // folded Wo split [k][n]
__device__ float2 g_trig[2048 * 32];                          // (cos, -sin) per (s, i)

// ---------------- helpers ----------------
__device__ __forceinline__ uint32_t saddr(const void* p) {
    return (uint32_t)__cvta_generic_to_shared(p);
}
__device__ __forceinline__ void split2(float x0, float x1, uint32_t& h, uint32_t& l) {
    __nv_bfloat162 H = __floats2bfloat162_rn(x0, x1);
    float f0 = __bfloat162float(H.x), f1 = __bfloat162float(H.y);
    __nv_bfloat162 L = __floats2bfloat162_rn(x0 - f0, x1 - f1);
    h = *(uint32_t*)&H; l = *(uint32_t*)&L;
}
__device__ __forceinline__ void mma16816(float* c, const uint32_t* a, uint32_t b0, uint32_t b1) {
    asm volatile(
        "mma.sync.aligned.m16n8k16.row.col.f32.bf16.bf16.f32 "
        "{%0,%1,%2,%3}, {%4,%5,%6,%7}, {%8,%9}, {%0,%1,%2,%3};"
        : "+f"(c[0]), "+f"(c[1]), "+f"(c[2]), "+f"(c[3])
        : "r"(a[0]), "r"(a[1]), "r"(a[2]), "r"(a[3]), "r"(b0), "r"(b1));
}
__device__ __forceinline__ void ldsm4(uint32_t* r, uint32_t a) {
    asm volatile("ldmatrix.sync.aligned.m8n8.x4.shared.b16 {%0,%1,%2,%3}, [%4];"
                 : "=r"(r[0]), "=r"(r[1]), "=r"(r[2]), "=r"(r[3]) : "r"(a));
}
__device__ __forceinline__ void ldsm4t(uint32_t* r, uint32_t a) {
    asm volatile("ldmatrix.sync.aligned.m8n8.x4.trans.shared.b16 {%0,%1,%2,%3}, [%4];"
                 : "=r"(r[0]), "=r"(r[1]), "=r"(r[2]), "=r"(r[3]) : "r"(a));
}
__device__ __forceinline__ void cpa16(uint32_t d, const void* g) {
    asm volatile("cp.async.cg.shared.global [%0], [%1], 16;" :: "r"(d), "l"(g));
}
#define CP_COMMIT() asm volatile("cp.async.commit_group;" ::: "memory")

// ---------------- fp32 -> split bf16 ----------------
__global__ void split4(const float* __restrict__ x, bf16* __restrict__ h,
                       bf16* __restrict__ l, int n)
{
    int i = (blockIdx.x * blockDim.x + threadIdx.x) * 4;
    if (i >= n) return;
    float4 v = *(const float4*)(x + i);
    uint32_t h0, l0, h1, l1;
    split2(v.x, v.y, h0, l0);
    split2(v.z, v.w, h1, l1);
    *(uint32_t*)(h + i) = h0; *(uint32_t*)(h + i + 2) = h1;
    *(uint32_t*)(l + i) = l0; *(uint32_t*)(l + i + 2) = l1;
}

// ---------------- concat Wq|Wk|Wv -> split [1024][2048] ----------------
__global__ void splitcat_w(const float* __restrict__ Wq, const float* __restrict__ Wk,
                           const float* __restrict__ Wv)
{
    const int idx = blockIdx.x * blockDim.x + threadIdx.x;   // 1024*2048
    const int k = idx >> 11, n = idx & 2047;
    const float v = (n < 1024) ? Wq[(size_t)k * 1024 + n]
                  : (n < 1536) ? Wk[(size_t)k * 512 + n - 1024]
                               : Wv[(size_t)k * 512 + n - 1536];
    bf16 vh = __float2bfloat16_rn(v);
    g_wch[idx] = vh;
    g_wcl[idx] = __float2bfloat16_rn(v - __bfloat162float(vh));
}

// ---------------- fold Wo rows for duplicated V features -> split ----------------
__global__ void fold_wo(const float* __restrict__ Wo)
{
    const int idx = blockIdx.x * blockDim.x + threadIdx.x;   // 512*1024
    const int i = idx >> 10, n = idx & 1023;
    const int j0 = (i >> 5) * 64 + (i & 31) * 2;
    const float w = Wo[(size_t)j0 * 1024 + n] + Wo[(size_t)(j0 + 1) * 1024 + n];
    bf16 wh = __float2bfloat16_rn(w);
    g_wofh[idx] = wh;
    g_wofl[idx] = __float2bfloat16_rn(w - __bfloat162float(wh));
}

// ---------------- trig table: (cos, -sin) of (s+1)*10^-i ----------------
__global__ void trig_init()
{
    const int idx = blockIdx.x * blockDim.x + threadIdx.x;   // 65536
    const int s = idx >> 5, i = idx & 31;
    float c, sn;
    sincosf((float)(s + 1) * exp10f(-(float)i), &c, &sn);
    g_trig[idx] = make_float2(c, -sn);                        // sign flip baked in
}

// ============== GEMM v2: split-bf16 3-term, 128x128 tiles, cp.async x2 =========
// A[M][K] row-major (h/l), B[K][N] row-major (h/l), C fp32 [M][ldc].
// 8 warps (2m x 4n), warp tile 64x32. dynamic smem: 2 stages x 37888B.
// stage layout (bytes): Ah 0 (128x40x2), Al 10240, Bh 20480 (32x136x2), Bl 29184.
__global__ void __launch_bounds__(256) gemm_v2(
    const bf16* __restrict__ Ah, const bf16* __restrict__ Al,
    const bf16* __restrict__ Bh, const bf16* __restrict__ Bl,
    float* __restrict__ C, int K, int ldb, int ldc)
{
    extern __shared__ char dsm[];
    const uint32_t sb = saddr(dsm);
    const int tid = threadIdx.x, wid = tid >> 5, lane = tid & 31;
    const int m0 = blockIdx.y * 128, n0 = blockIdx.x * 128;
    const int mw = (wid >> 2) * 64, nw = (wid & 3) * 32;
    const int NK = K >> 5;

    float c[4][4][4];
#pragma unroll
    for (int mt = 0; mt < 4; mt++)
#pragma unroll
        for (int nt = 0; nt < 4; nt++)
#pragma unroll
            for (int k = 0; k < 4; k++) c[mt][nt][k] = 0.f;

    const int arow = tid >> 1, ac = (tid & 1) * 16;   // A: 2 thr/row, 2x8-elem chunks
    const int brow = tid >> 3, bc = (tid & 7) * 16;   // B: 8 thr/row, 2x8-elem chunks

    auto load_chunk = [&](int ch) {
        const uint32_t stg = sb + (uint32_t)(ch & 1) * 37888u;
        const int k0 = ch * 32;
        const bf16* ag = Ah + (size_t)(m0 + arow) * K + k0 + ac;
        const bf16* alg = Al + (size_t)(m0 + arow) * K + k0 + ac;
        const uint32_t adst = stg + arow * 80 + ac * 2;
        cpa16(adst,           ag);
        cpa16(adst + 16,      ag + 8);
        cpa16(adst + 10240,      alg);
        cpa16(adst + 10240 + 16, alg + 8);
        const bf16* bg = Bh + (size_t)(k0 + brow) * ldb + n0 + bc;
        const bf16* blg = Bl + (size_t)(k0 + brow) * ldb + n0 + bc;
        const uint32_t bdst = stg + 20480 + brow * 272 + bc * 2;
        cpa16(bdst,          bg);
        cpa16(bdst + 16,     bg + 8);
        cpa16(bdst + 8704,      blg);
        cpa16(bdst + 8704 + 16, blg + 8);
        CP_COMMIT();
    };

    load_chunk(0);
    load_chunk(1);

    for (int ch = 0; ch < NK; ch++) {
        if (ch + 1 < NK) asm volatile("cp.async.wait_group 1;" ::: "memory");
        else             asm volatile("cp.async.wait_group 0;" ::: "memory");
        __syncthreads();
        const uint32_t stg = sb + (uint32_t)(ch & 1) * 37888u;

#pragma unroll
        for (int kk = 0; kk < 32; kk += 16) {
            uint32_t ah[4][4], al[4][4];
#pragma unroll
            for (int mt = 0; mt < 4; mt++) {
                const int rr = mw + mt * 16 + (lane & 15);
                const int cc = kk + (lane >> 4) * 8;
                const uint32_t a = stg + rr * 80 + cc * 2;
                ldsm4(ah[mt], a);
                ldsm4(al[mt], a + 10240);
            }
            uint32_t bh[4][2], bl[4][2];
#pragma unroll
            for (int np = 0; np < 2; np++) {
                const int rr = kk + (lane & 7) + ((lane >> 3) & 1) * 8;
                const int cc = nw + np * 16 + (lane >> 4) * 8;
                const uint32_t a = stg + 20480 + rr * 272 + cc * 2;
                uint32_t r4[4];
                ldsm4t(r4, a);
                bh[np*2][0] = r4[0]; bh[np*2][1] = r4[1];
                bh[np*2+1][0] = r4[2]; bh[np*2+1][1] = r4[3];
                ldsm4t(r4, a + 8704);
                bl[np*2][0] = r4[0]; bl[np*2][1] = r4[1];
                bl[np*2+1][0] = r4[2]; bl[np*2+1][1] = r4[3];
            }
#pragma unroll
            for (int mt = 0; mt < 4; mt++)
#pragma unroll
                for (int nt = 0; nt < 4; nt++) {
                    mma16816(c[mt][nt], ah[mt], bh[nt][0], bh[nt][1]);
                    mma16816(c[mt][nt], ah[mt], bl[nt][0], bl[nt][1]);
                    mma16816(c[mt][nt], al[mt], bh[nt][0], bh[nt][1]);
                }
        }
        __syncthreads();
        if (ch + 2 < NK) load_chunk(ch + 2);
    }

#pragma unroll
    for (int mt = 0; mt < 4; mt++) {
        const int r0 = m0 + mw + mt * 16 + (lane >> 2);
#pragma unroll
        for (int nt = 0; nt < 4; nt++) {
            const int cc = n0 + nw + nt * 8 + (lane & 3) * 2;
            *(float2*)&C[(size_t)r0 * ldc + cc]       = make_float2(c[mt][nt][0], c[mt][nt][1]);
            *(float2*)&C[(size_t)(r0 + 8) * ldc + cc] = make_float2(c[mt][nt][2], c[mt][nt][3]);
        }
    }
}

// ---------------- RoPE (verified flipped rotation) -> split bf16, row-major ----
__global__ void rope_scatter(const float* __restrict__ X)
{
    const int row = blockIdx.x;           // b*2048 + s
    const int s = row & (SEQ - 1), b = row >> 11;
    const int t = threadIdx.x;            // 0..511
    const int h = t >> 5, i = t & 31;
    const float* xr = X + (size_t)row * 2048;

    const float2 tr = g_trig[s * 32 + i];
    const float c = tr.x, sn = tr.y;      // (cos, -sin): flip baked in table

    const size_t bh = (size_t)(b * NH + h);
    const size_t base = (bh * SEQ + s) * 64 + 2 * i;

    const float xe = xr[h * 64 + 2 * i];
    const float xo = xr[h * 64 + 2 * i + 1];
    uint32_t hh, ll;
    split2((xe * c - xo * sn) * 0.5f, (xe * sn + xo * c) * 0.5f, hh, ll);
    *(uint32_t*)&g_Qh[base] = hh; *(uint32_t*)&g_Ql[base] = ll;

    const float ko = xr[1024 + h * 32 + i];
    split2(ko * (c - sn), ko * (c + sn), hh, ll);
    *(uint32_t*)&g_Kh[base] = hh; *(uint32_t*)&g_Kl[base] = ll;

    const float v = xr[1536 + t];
    const size_t vb = (bh * SEQ + s) * 32 + i;
    bf16 vh = __float2bfloat16_rn(v);
    g_Vh[vb] = vh;
    g_Vl[vb] = __float2bfloat16_rn(v - __bfloat162float(vh));
}

// ============== flash attention v2: split-bf16 mma + cp.async x2 ===============
// stage layout (bytes): Kh 0 (64x72x2), Kl 9216, Vh 18432 (64x40x2), Vl 23552.
// stage stride 28672, 2 stages.
__global__ void __launch_bounds__(256) flash_mma()
{
    extern __shared__ char dsm[];
    const uint32_t sb = saddr(dsm);
    const int tid = threadIdx.x, wid = tid >> 5, lane = tid & 31;
    const int bh = blockIdx.y, q0 = blockIdx.x * 128;
    const int b = bh >> 4, h = bh & 15;
    const int r = lane >> 2, c2 = (lane & 3) * 2;

    uint32_t qh[4][4], ql[4][4];
    {
        const size_t qrow = ((size_t)bh * SEQ + q0 + wid * 16 + r) * 64;
#pragma unroll
        for (int kk = 0; kk < 4; kk++) {
            const size_t o0 = qrow + kk * 16 + c2;
            qh[kk][0] = *(const uint32_t*)&g_Qh[o0];
            qh[kk][1] = *(const uint32_t*)&g_Qh[o0 + 8u * 64];
            qh[kk][2] = *(const uint32_t*)&g_Qh[o0 + 8];
            qh[kk][3] = *(const uint32_t*)&g_Qh[o0 + 8u * 64 + 8];
            ql[kk][0] = *(const uint32_t*)&g_Ql[o0];
            ql[kk][1] = *(const uint32_t*)&g_Ql[o0 + 8u * 64];
            ql[kk][2] = *(const uint32_t*)&g_Ql[o0 + 8];
            ql[kk][3] = *(const uint32_t*)&g_Ql[o0 + 8u * 64 + 8];
        }
    }

    float o[4][4];
#pragma unroll
    for (int nt = 0; nt < 4; nt++)
#pragma unroll
        for (int k = 0; k < 4; k++) o[nt][k] = 0.f;
    float m0r = -1e30f, m1r = -1e30f, l0r = 0.f, l1r = 0.f;

    const bf16* Khg = g_Kh + (size_t)bh * SEQ * 64;
    const bf16* Klg = g_Kl + (size_t)bh * SEQ * 64;
    const bf16* Vhg = g_Vh + (size_t)bh * SEQ * 32;
    const bf16* Vlg = g_Vl + (size_t)bh * SEQ * 32;

    const int krow = tid >> 2, kq = tid & 3;

    auto load_tile = [&](int it) {
        const int k0 = it * 64;
        const uint32_t stg = sb + (uint32_t)(it & 1) * 28672u;
        const bf16* kh = Khg + (size_t)(k0 + krow) * 64 + kq * 16;
        const bf16* kl = Klg + (size_t)(k0 + krow) * 64 + kq * 16;
        const uint32_t kdst = stg + krow * 144 + kq * 32;
        cpa16(kdst,          kh);
        cpa16(kdst + 16,     kh + 8);
        cpa16(kdst + 9216,      kl);
        cpa16(kdst + 9216 + 16, kl + 8);
        cpa16(stg + 18432 + krow * 80 + kq * 16, Vhg + (size_t)(k0 + krow) * 32 + kq * 8);
        cpa16(stg + 23552 + krow * 80 + kq * 16, Vlg + (size_t)(k0 + krow) * 32 + kq * 8);
        CP_COMMIT();
    };

    load_tile(0);
    load_tile(1);

    for (int it = 0; it < 32; it++) {
        if (it < 31) asm volatile("cp.async.wait_group 1;" ::: "memory");
        else         asm volatile("cp.async.wait_group 0;" ::: "memory");
        __syncthreads();
        const uint32_t stg = sb + (uint32_t)(it & 1) * 28672u;

        // S = Q K^T
        float s[8][4];
#pragma unroll
        for (int nt = 0; nt < 8; nt++)
#pragma unroll
            for (int k = 0; k < 4; k++) s[nt][k] = 0.f;

#pragma unroll
        for (int kk = 0; kk < 4; kk++) {
#pragma unroll
            for (int np = 0; np < 4; np++) {
                const int rr = np * 16 + (lane & 7) + ((lane >> 4) << 3);
                const int cc = kk * 16 + ((lane >> 3) & 1) * 8;
                const uint32_t a = stg + rr * 144 + cc * 2;
                uint32_t rH[4], rL[4];
                ldsm4(rH, a);
                ldsm4(rL, a + 9216);
#pragma unroll
                for (int t2 = 0; t2 < 2; t2++) {
                    const int nt = np * 2 + t2;
                    mma16816(s[nt], qh[kk], rH[t2*2], rH[t2*2+1]);
                    mma16816(s[nt], qh[kk], rL[t2*2], rL[t2*2+1]);
                    mma16816(s[nt], ql[kk], rH[t2*2], rH[t2*2+1]);
                }
            }
        }

        // online softmax
        float mx0 = -1e30f, mx1 = -1e30f;
#pragma unroll
        for (int nt = 0; nt < 8; nt++) {
            mx0 = fmaxf(mx0, fmaxf(s[nt][0], s[nt][1]));
            mx1 = fmaxf(mx1, fmaxf(s[nt][2], s[nt][3]));
        }
        mx0 = fmaxf(mx0, __shfl_xor_sync(0xffffffffu, mx0, 1));
        mx0 = fmaxf(mx0, __shfl_xor_sync(0xffffffffu, mx0, 2));
        mx1 = fmaxf(mx1, __shfl_xor_sync(0xffffffffu, mx1, 1));
        mx1 = fmaxf(mx1, __shfl_xor_sync(0xffffffffu, mx1, 2));
        const float mn0 = fmaxf(m0r, mx0), mn1 = fmaxf(m1r, mx1);
        const float cr0 = __expf(m0r - mn0), cr1 = __expf(m1r - mn1);
        float sum0 = 0.f, sum1 = 0.f;
#pragma unroll
        for (int nt = 0; nt < 8; nt++) {
            s[nt][0] = __expf(s[nt][0] - mn0); sum0 += s[nt][0];
            s[nt][1] = __expf(s[nt][1] - mn0); sum0 += s[nt][1];
            s[nt][2] = __expf(s[nt][2] - mn1); sum1 += s[nt][2];
            s[nt][3] = __expf(s[nt][3] - mn1); sum1 += s[nt][3];
        }
        sum0 += __shfl_xor_sync(0xffffffffu, sum0, 1);
        sum0 += __shfl_xor_sync(0xffffffffu, sum0, 2);
        sum1 += __shfl_xor_sync(0xffffffffu, sum1, 1);
        sum1 += __shfl_xor_sync(0xffffffffu, sum1, 2);
        l0r = l0r * cr0 + sum0;
        l1r = l1r * cr1 + sum1;
        m0r = mn0; m1r = mn1;
#pragma unroll
        for (int nt = 0; nt < 4; nt++) {
            o[nt][0] *= cr0; o[nt][1] *= cr0;
            o[nt][2] *= cr1; o[nt][3] *= cr1;
        }

        uint32_t ph[4][4], pl[4][4];
#pragma unroll
        for (int kk = 0; kk < 4; kk++) {
            split2(s[2*kk][0],   s[2*kk][1],   ph[kk][0], pl[kk][0]);
            split2(s[2*kk][2],   s[2*kk][3],   ph[kk][1], pl[kk][1]);
            split2(s[2*kk+1][0], s[2*kk+1][1], ph[kk][2], pl[kk][2]);
            split2(s[2*kk+1][2], s[2*kk+1][3], ph[kk][3], pl[kk][3]);
        }

        // O += P V
#pragma unroll
        for (int kk = 0; kk < 4; kk++) {
#pragma unroll
            for (int np = 0; np < 2; np++) {
                const int rr = kk * 16 + (lane & 7) + ((lane >> 3) & 1) * 8;
                const int cc = np * 16 + (lane >> 4) * 8;
                const uint32_t a = stg + 18432 + rr * 80 + cc * 2;
                uint32_t rH[4], rL[4];
                ldsm4t(rH, a);
                ldsm4t(rL, a + 5120);
#pragma unroll
                for (int t2 = 0; t2 < 2; t2++) {
                    const int nt = np * 2 + t2;
                    mma16816(o[nt], ph[kk], rH[t2*2], rH[t2*2+1]);
                    mma16816(o[nt], ph[kk], rL[t2*2], rL[t2*2+1]);
                    mma16816(o[nt], pl[kk], rH[t2*2], rH[t2*2+1]);
                }
            }
        }
        __syncthreads();
        if (it + 2 < 32) load_tile(it + 2);
    }

    const float i0 = 1.f / l0r, i1 = 1.f / l1r;
    const size_t row0 = (size_t)b * SEQ + q0 + wid * 16 + r;
#pragma unroll
    for (int nt = 0; nt < 4; nt++) {
        const int cc = h * 32 + nt * 8 + c2;
        uint32_t hh, ll;
        split2(o[nt][0] * i0, o[nt][1] * i0, hh, ll);
        *(uint32_t*)&g_ofh[row0 * 512 + cc] = hh;
        *(uint32_t*)&g_ofl[row0 * 512 + cc] = ll;
        split2(o[nt][2] * i1, o[nt][3] * i1, hh, ll);
        *(uint32_t*)&g_ofh[(row0 + 8) * 512 + cc] = hh;
        *(uint32_t*)&g_ofl[(row0 + 8) * 512 + cc] = ll;
    }
}

// ---------------- launch ----------------
extern "C" void kernel_launch(void* const* d_in, const int* in_sizes, int n_in,
                              void* d_out, int out_size)
{
    int iq = 0, i1M[2] = {2, 5}, i05[2] = {3, 4};
    {
        int n1 = 0, n0 = 0;
        for (int i = 0; i < n_in; i++) {
            const int sz = in_sizes[i];
            if (sz == 4194304) iq = i;
            else if (sz == 1048576) { if (n1 < 2) i1M[n1++] = i; }
            else if (sz == 524288)  { if (n0 < 2) i05[n0++] = i; }
        }
    }
    const bool alpha = (iq != 0);
    const float* q  = (const float*)d_in[iq];
    const float* Wq = (const float*)d_in[alpha ? i1M[1] : i1M[0]];
    const float* Wo = (const float*)d_in[alpha ? i1M[0] : i1M[1]];
    const float* Wk = (const float*)d_in[i05[0]];
    const float* Wv = (const float*)d_in[i05[1]];
    float* out = (float*)d_out;

    float* XQKV;  cudaGetSymbolAddress((void**)&XQKV, g_XQKV);
    bf16 *qh, *ql, *wch, *wcl, *ofh, *ofl, *wofh, *wofl;
    cudaGetSymbolAddress((void**)&qh, g_qh);     cudaGetSymbolAddress((void**)&ql, g_ql);
    cudaGetSymbolAddress((void**)&wch, g_wch);   cudaGetSymbolAddress((void**)&wcl, g_wcl);
    cudaGetSymbolAddress((void**)&ofh, g_ofh);   cudaGetSymbolAddress((void**)&ofl, g_ofl);
    cudaGetSymbolAddress((void**)&wofh, g_wofh); cudaGetSymbolAddress((void**)&wofl, g_wofl);

    const int GEMM_SMEM = 2 * 37888;
    const int FLASH_SMEM = 2 * 28672;
    cudaFuncSetAttribute(gemm_v2,  cudaFuncAttributeMaxDynamicSharedMemorySize, GEMM_SMEM);
    cudaFuncSetAttribute(flash_mma, cudaFuncAttributeMaxDynamicSharedMemorySize, FLASH_SMEM);

    // prep
    trig_init<<<256, 256>>>();
    split4<<<4096, 256>>>(q, qh, ql, 4194304);
    splitcat_w<<<8192, 256>>>(Wq, Wk, Wv);
    fold_wo<<<2048, 256>>>(Wo);

    // fused QKV projection (one GEMM, N = 2048)
    gemm_v2<<<dim3(16, 32), 256, GEMM_SMEM>>>(qh, ql, wch, wcl, XQKV, 1024, 2048, 2048);

    rope_scatter<<<4096, 512>>>(XQKV);
    flash_mma<<<dim3(16, 32), 256, FLASH_SMEM>>>();

    // output projection (folded Wo, K = 512)
    gemm_v2<<<dim3(8, 32), 256, GEMM_SMEM>>>(ofh, ofl, wofh, wofl, out, 512, 1024, 1024);
}